// round 14
// baseline (speedup 1.0000x reference)
#include <cuda_runtime.h>
#include <math.h>

// ---------------- problem constants (fixed shapes from setup_inputs) -------
#define NB      32          // batch
#define TSAMP   160000      // samples per batch
#define KFFT    1024        // n_fft
#define MWIN    800         // win_length
#define HOP     600
#define NBINS   256
#define NF      267         // 1 + (160000+1024-1024)/600
#define NFP     134         // frame pairs (two real frames per complex FFT)
#define LMAXW   13
#define LMINW   3
#define FT      (NBINS*NF)  // 68352 (worst-case valid keys per batch)
#define SMEMK   8192        // median smem key cache capacity

#define PHI1(a) ((a) + 4 * ((a) >> 4))   // skew for stage1->stage2 buffer
#define TWI(i)  ((i) + ((i) >> 4))       // skewed twiddle index (CF strided reads)

__device__ __forceinline__ float2 cmul(float2 a, float2 b) {
    return make_float2(a.x * b.x - a.y * b.y, a.x * b.y + a.y * b.x);
}

// ---------------- scratch (__device__ globals, no allocation) --------------
__device__ float        g_Yt[NB*NF*NBINS];      // [B, T, F]: stft-coalesced
__device__ unsigned int g_keys[NB*FT];          // compacted valid keys
__device__ int          g_nvalid[NB];

// ---------------- STFT power: one block per (batch, frame-pair) ------------
// Two real frames packed as re/im of one complex 1024-pt FFT (radix-4
// Stockham autosort). Interior blocks (132 of 134) take a branchless load
// path; Hann window cached in smem; input register-resident through stage 0;
// 1 twiddle load per stage; trimmed final stage; coalesced [B,T,F] stores.
__global__ __launch_bounds__(256) void stft_kernel(const float* __restrict__ y) {
    const int p  = blockIdx.x % NFP;
    const int b  = blockIdx.x / NFP;
    const int fa = 2 * p;
    const int fb = 2 * p + 1;                    // may be NF (dropped)
    __shared__ __align__(16) float2 A[1280];
    __shared__ __align__(16) float2 B[1024];
    __shared__ float2 stw[272];
    __shared__ float  win[MWIN];
    const int tid = threadIdx.x;

    if (p == 0 && tid == 0) g_nvalid[b] = 0;     // replay-state reset

    {   // twiddle table: exp(-2*pi*i*k/1024), k<256, skew-stored
        float s, c;
        sincospif(-(float)tid / 512.0f, &s, &c);
        stw[TWI(tid)] = make_float2(c, s);
    }
    for (int i = tid; i < MWIN; i += 256)        // periodic hann
        win[i] = 0.5f - 0.5f * cospif((float)i / 400.0f);
    __syncthreads();

    // windowed input, elements tid+256q held in registers (natural order)
    const float* yb = y + (size_t)b * TSAMP;
    float2 v[4];
    if (p >= 1 && p <= 132) {                    // interior: no reflect/bounds
        const float* pa = yb + fa * HOP - 512;
        const float* pb = yb + fb * HOP - 512;
        #pragma unroll
        for (int q = 0; q < 4; q++) {
            int j = tid + q * 256;
            float va = 0.0f, vb = 0.0f;
            if (j >= 112 && j < 912) {
                float w = win[j - 112];
                va = __ldg(pa + j) * w;
                vb = __ldg(pb + j) * w;
            }
            v[q] = make_float2(va, vb);
        }
    } else {                                     // edge frames: reflect pad
        #pragma unroll
        for (int q = 0; q < 4; q++) {
            int j = tid + q * 256;
            float va = 0.0f, vb = 0.0f;
            if (j >= 112 && j < 912) {
                float w = win[j - 112];
                int sa = fa * HOP + j - 512;
                if (sa < 0) sa = -sa;
                else if (sa >= TSAMP) sa = 2 * (TSAMP - 1) - sa;
                va = __ldg(yb + sa) * w;
                if (fb < NF) {
                    int sb = fb * HOP + j - 512;
                    if (sb < 0) sb = -sb;
                    else if (sb >= TSAMP) sb = 2 * (TSAMP - 1) - sb;
                    vb = __ldg(yb + sb) * w;
                }
            }
            v[q] = make_float2(va, vb);
        }
    }

    // stage 0 (Ns=1, twiddles = 1): registers -> B, contiguous STS.128 x2
    {
        float2 t0 = {v[0].x + v[2].x, v[0].y + v[2].y};
        float2 t1 = {v[0].x - v[2].x, v[0].y - v[2].y};
        float2 t2 = {v[1].x + v[3].x, v[1].y + v[3].y};
        float2 t3 = {v[1].x - v[3].x, v[1].y - v[3].y};
        ((float4*)B)[2 * tid]     = make_float4(t0.x + t2.x, t0.y + t2.y,
                                                t1.x + t3.y, t1.y - t3.x);
        ((float4*)B)[2 * tid + 1] = make_float4(t0.x - t2.x, t0.y - t2.y,
                                                t1.x - t3.y, t1.y + t3.x);
    }
    __syncthreads();

    #define BFLY(w1, v0, v1, v2, v3, o0, o1, o2, o3)                          \
        {                                                                     \
            float2 w2 = cmul(w1, w1), w3 = cmul(w1, w2);                      \
            float2 a1 = cmul(w1, v1), a2 = cmul(w2, v2), a3 = cmul(w3, v3);   \
            float2 t0 = {v0.x + a2.x, v0.y + a2.y};                           \
            float2 t1 = {v0.x - a2.x, v0.y - a2.y};                           \
            float2 t2 = {a1.x + a3.x, a1.y + a3.y};                           \
            float2 t3 = {a1.x - a3.x, a1.y - a3.y};                           \
            o0 = make_float2(t0.x + t2.x, t0.y + t2.y);                       \
            o1 = make_float2(t1.x + t3.y, t1.y - t3.x);                       \
            o2 = make_float2(t0.x - t2.x, t0.y - t2.y);                       \
            o3 = make_float2(t1.x - t3.y, t1.y + t3.x);                       \
        }

    // stage 1 (Ns=4): B -> A (PHI1 layout)
    {
        const int m = tid & 3;
        float2 v0 = B[tid], v1 = B[tid + 256], v2 = B[tid + 512], v3 = B[tid + 768];
        float2 w1 = stw[TWI(m * 64)];
        float2 o0, o1, o2, o3;
        BFLY(w1, v0, v1, v2, v3, o0, o1, o2, o3);
        const int base = ((tid >> 2) << 4) + m;
        A[PHI1(base)]      = o0; A[PHI1(base + 4)]  = o1;
        A[PHI1(base + 8)]  = o2; A[PHI1(base + 12)] = o3;
    }
    __syncthreads();

    // stage 2 (Ns=16): A (PHI1) -> B (identity)
    {
        const int m = tid & 15;
        float2 v0 = A[PHI1(tid)],       v1 = A[PHI1(tid + 256)];
        float2 v2 = A[PHI1(tid + 512)], v3 = A[PHI1(tid + 768)];
        float2 w1 = stw[TWI(m * 16)];
        float2 o0, o1, o2, o3;
        BFLY(w1, v0, v1, v2, v3, o0, o1, o2, o3);
        const int base = ((tid >> 4) << 6) + m;
        B[base]      = o0; B[base + 16] = o1;
        B[base + 32] = o2; B[base + 48] = o3;
    }
    __syncthreads();

    // stage 3 (Ns=64): B -> A (identity)
    {
        const int m = tid & 63;
        float2 v0 = B[tid], v1 = B[tid + 256], v2 = B[tid + 512], v3 = B[tid + 768];
        float2 w1 = stw[TWI(m * 4)];
        float2 o0, o1, o2, o3;
        BFLY(w1, v0, v1, v2, v3, o0, o1, o2, o3);
        const int base = ((tid >> 6) << 8) + m;
        A[base]       = o0; A[base + 64]  = o1;
        A[base + 128] = o2; A[base + 192] = o3;
    }
    __syncthreads();

    // stage 4 (Ns=256, trimmed): Z[tid] stays in regs; only Z[tid+768] -> smem
    float2 zk;
    {
        float2 v0 = A[tid], v1 = A[tid + 256], v2 = A[tid + 512], v3 = A[tid + 768];
        float2 w1 = stw[TWI(tid)];
        float2 w2 = cmul(w1, w1), w3 = cmul(w1, w2);
        float2 a1 = cmul(w1, v1), a2 = cmul(w2, v2), a3 = cmul(w3, v3);
        float2 t0 = {v0.x + a2.x, v0.y + a2.y};
        float2 t1 = {v0.x - a2.x, v0.y - a2.y};
        float2 t2 = {a1.x + a3.x, a1.y + a3.y};
        float2 t3 = {a1.x - a3.x, a1.y - a3.y};
        zk = make_float2(t0.x + t2.x, t0.y + t2.y);          // Z[tid]
        B[768 + tid] = make_float2(t1.x - t3.y, t1.y + t3.x); // Z[tid+768]
    }
    __syncthreads();

    // Hermitian unpack; power, layout [B, T, F] -> coalesced 256-bin stores
    float2 zc = (tid == 0) ? zk : B[1024 - tid];  // Z[K - tid]
    float xar = 0.5f * (zk.x + zc.x), xai = 0.5f * (zk.y - zc.y);
    float ddr = zk.x - zc.x,          ddi = zk.y + zc.y;
    float xbr = 0.5f * ddi,           xbi = -0.5f * ddr;
    g_Yt[((size_t)b * NF + fa) * NBINS + tid] = xar * xar + xai * xai;
    if (fb < NF)
        g_Yt[((size_t)b * NF + fb) * NBINS + tid] = xbr * xbr + xbi * xbi;
}

// ---------------- RT60: 4 subbands per block, float4 loads ------------------
__global__ __launch_bounds__(128) void rt60_kernel() {
    const int g  = blockIdx.x;                   // 2048 blocks
    const int b  = g >> 6;                       // 64 groups of 4 f per batch
    const int f0 = (g & 63) * 4;
    __shared__ float        sy4[4][272];
    __shared__ unsigned int W[12];               // decrease-flag bitmask
    __shared__ unsigned int skey[NF];
    __shared__ int          sbest;
    __shared__ int          scnt;
    __shared__ int          sbase;
    const int tid  = threadIdx.x;
    const int lane = tid & 31;
    if (tid < 12) W[tid] = 0u;                   // W[9..11] stay 0 forever

    // one coalesced float4 per (t): columns f0..f0+3
    const float* bp = g_Yt + (size_t)b * NF * NBINS + f0;
    for (int t = tid; t < NF; t += 128) {
        float4 vv = *(const float4*)(bp + (size_t)t * NBINS);
        sy4[0][t] = vv.x; sy4[1][t] = vv.y; sy4[2][t] = vv.z; sy4[3][t] = vv.w;
    }

    #pragma unroll 1
    for (int r = 0; r < 4; r++) {
        const float* sy = sy4[r];
        __syncthreads();                         // loads done / prior row done
        if (tid == 0) { sbest = 0; scnt = 0; }
        __syncthreads();

        // pack strict-decrease flags into bitmask words via ballot
        #pragma unroll
        for (int base = 0; base < 288; base += 128) {
            int t = base + tid;
            bool flag = (t + 1 < NF) && (sy[t + 1] < sy[t]);
            unsigned int m = __ballot_sync(0xFFFFFFFFu, flag);
            if (lane == 0 && (t >> 5) < 9) W[t >> 5] = m;
        }
        __syncthreads();

        // best window length: run length from t = ffs of first zero bit
        int localbest = 0;
        for (int t = tid; t < NF; t += 128) {
            int w = t >> 5, rr = t & 31;
            unsigned int bits = (W[w] >> rr) | (rr ? (W[w + 1] << (32 - rr)) : 0u);
            unsigned int nb = ~bits;
            int c = nb ? (__ffs(nb) - 1) : 32;
            if (c > LMAXW - 1) c = LMAXW - 1;
            int cand = c + 1;
            int rem  = NF - t;
            if (cand > rem) cand = rem;
            if (cand > localbest) localbest = cand;
        }
        atomicMax(&sbest, localbest);
        __syncthreads();

        const int lenL = sbest;                  // block-uniform
        if (lenL < LMINW) continue;              // no decreasing window

        const float xm  = 0.5f * (float)(lenL - 1);
        const float den = (float)lenL * (float)(lenL * lenL - 1) / 12.0f;

        for (int t = tid; t < NF; t += 128) {
            int w = t >> 5, rr = t & 31;
            unsigned int bits = (W[w] >> rr) | (rr ? (W[w + 1] << (32 - rr)) : 0u);
            unsigned int nb = ~bits;
            int c = nb ? (__ffs(nb) - 1) : 32;
            if (t + lenL <= NF && c >= lenL - 1) {
                // EDC: reverse cumsum in same order as reference, then dB
                float acc = 0.0f;
                float db[LMAXW];
                for (int j = lenL - 1; j >= 0; j--) {
                    acc += sy[t + j];
                    db[j] = 10.0f * log10f(fmaxf(acc, 1e-10f));
                }
                float d0 = db[0];
                if (db[lenL - 1] - d0 < -10.0f) {    // selected
                    float num = 0.0f;
                    for (int j = 1; j < lenL; j++)
                        num += ((float)j - xm) * (db[j] - d0);
                    float slope = num / den;         // slope <= 0 here
                    float rt60  = (-60.0f / slope) * 0.0375f;  // HOP/FS
                    unsigned int u = __float_as_uint(rt60);
                    unsigned int key = (u & 0x80000000u) ? ~u : (u | 0x80000000u);
                    int pos = atomicAdd(&scnt, 1);
                    skey[pos] = key;
                }
            }
        }
        __syncthreads();

        const int cnt = scnt;
        if (cnt > 0) {                           // block-uniform (scnt shared)
            if (tid == 0) sbase = atomicAdd(&g_nvalid[b], cnt);
            __syncthreads();
            unsigned int* dst = g_keys + (size_t)b * FT + sbase;
            for (int i = tid; i < cnt; i += 128) dst[i] = skey[i];
        }
    }
}

// ---------------- median: one block per batch, 4-pass radix select ----------
__global__ __launch_bounds__(512) void median_kernel(const float* __restrict__ coeffs,
                                                     float* __restrict__ out) {
    const int b   = blockIdx.x;
    const int tid = threadIdx.x;
    __shared__ unsigned int skeys[SMEMK];
    __shared__ int          hist[256];
    __shared__ unsigned int s_pfx;
    __shared__ int          s_k;

    const int n = g_nvalid[b];
    if (n == 0) {
        if (tid == 0) out[b] = 0.5f;             // DEFAULT_RT60 (>= 0.01)
        return;
    }
    const unsigned int* gk = g_keys + (size_t)b * FT;
    const bool fits = (n <= SMEMK);
    if (fits)
        for (int i = tid; i < n; i += 512) skeys[i] = gk[i];
    if (tid == 0) { s_pfx = 0u; s_k = (n - 1) >> 1; }
    __syncthreads();

    #pragma unroll
    for (int pass = 0; pass < 4; pass++) {
        for (int i = tid; i < 256; i += 512) hist[i] = 0;
        __syncthreads();
        const int shift = 24 - 8 * pass;
        const unsigned int pfx   = s_pfx;
        const unsigned int hmask = (pass == 0) ? 0u : (0xFFFFFFFFu << (shift + 8));
        if (fits) {
            for (int i = tid; i < n; i += 512) {
                unsigned int key = skeys[i];
                if ((key & hmask) == pfx) atomicAdd(&hist[(key >> shift) & 255], 1);
            }
        } else {
            for (int i = tid; i < n; i += 512) {
                unsigned int key = gk[i];
                if ((key & hmask) == pfx) atomicAdd(&hist[(key >> shift) & 255], 1);
            }
        }
        __syncthreads();

        if (tid < 32) {                          // warp-scan bin select
            const int lane = tid;
            const int base = lane * 8;
            int c[8]; int s = 0;
            #pragma unroll
            for (int q = 0; q < 8; q++) { c[q] = hist[base + q]; s += c[q]; }
            int excl = s;
            #pragma unroll
            for (int off = 1; off < 32; off <<= 1) {
                int nn = __shfl_up_sync(0xFFFFFFFFu, excl, off);
                if (lane >= off) excl += nn;
            }
            excl -= s;                           // exclusive prefix across lanes
            const int k0 = s_k;
            int bin = 256, cumAt = 0, cum = excl;
            #pragma unroll
            for (int q = 0; q < 8; q++) {
                if (bin == 256 && cum + c[q] > k0) { bin = base + q; cumAt = cum; }
                cum += c[q];
            }
            unsigned int ball = __ballot_sync(0xFFFFFFFFu, bin < 256);
            int src = __ffs(ball) - 1;           // guaranteed: total >= k0+1
            if (lane == src) {
                s_k   = k0 - cumAt;
                s_pfx = pfx | ((unsigned int)bin << shift);
            }
        }
        __syncthreads();
    }

    if (tid == 0) {
        unsigned int key = s_pfx;
        unsigned int u = (key & 0x80000000u) ? (key ^ 0x80000000u) : ~key;
        float med = __uint_as_float(u);
        out[b] = fmaxf(coeffs[0] + coeffs[1] * med, 0.01f);
    }
}

// ---------------- launcher ---------------------------------------------------
extern "C" void kernel_launch(void* const* d_in, const int* in_sizes, int n_in,
                              void* d_out, int out_size) {
    const float* y      = (const float*)d_in[0];
    const float* coeffs = (const float*)d_in[1];
    float*       out    = (float*)d_out;

    stft_kernel<<<NB * NFP, 256>>>(y);
    rt60_kernel<<<NB * NBINS / 4, 128>>>();
    median_kernel<<<NB, 512>>>(coeffs, out);
}

// round 15
// speedup vs baseline: 1.0199x; 1.0199x over previous
#include <cuda_runtime.h>
#include <math.h>

// ---------------- problem constants (fixed shapes from setup_inputs) -------
#define NB      32          // batch
#define TSAMP   160000      // samples per batch
#define KFFT    1024        // n_fft
#define MWIN    800         // win_length
#define HOP     600
#define NBINS   256
#define NF      267         // 1 + (160000+1024-1024)/600
#define NFP     134         // frame pairs (two real frames per complex FFT)
#define LMAXW   13
#define LMINW   3
#define FT      (NBINS*NF)  // 68352 (worst-case valid keys per batch)
#define SMEMK   8192        // median smem key cache capacity

#define PHI1(a) ((a) + 4 * ((a) >> 4))   // skew for stage1->stage2 buffer
#define TWI(i)  ((i) + ((i) >> 4))       // skewed twiddle index (CF strided reads)

__device__ __forceinline__ float2 cmul(float2 a, float2 b) {
    return make_float2(a.x * b.x - a.y * b.y, a.x * b.y + a.y * b.x);
}

// ---------------- scratch (__device__ globals, no allocation) --------------
__device__ float        g_Yt[NB*NF*NBINS];      // [B, T, F]: stft-coalesced
__device__ unsigned int g_keys[NB*FT];          // compacted valid keys
__device__ int          g_nvalid[NB];

// ---------------- STFT power: one block per (batch, frame-pair) ------------
// Two real frames packed as re/im of one complex 1024-pt FFT (radix-4
// Stockham autosort). Interior blocks (132 of 134) take a branchless load
// path; Hann window cached in smem; input register-resident through stage 0;
// 1 twiddle load per stage; trimmed final stage; coalesced [B,T,F] stores.
__global__ __launch_bounds__(256) void stft_kernel(const float* __restrict__ y) {
    const int p  = blockIdx.x % NFP;
    const int b  = blockIdx.x / NFP;
    const int fa = 2 * p;
    const int fb = 2 * p + 1;                    // may be NF (dropped)
    __shared__ __align__(16) float2 A[1280];
    __shared__ __align__(16) float2 B[1024];
    __shared__ float2 stw[272];
    __shared__ float  win[MWIN];
    const int tid = threadIdx.x;

    if (p == 0 && tid == 0) g_nvalid[b] = 0;     // replay-state reset

    {   // twiddle table: exp(-2*pi*i*k/1024), k<256, skew-stored
        float s, c;
        sincospif(-(float)tid / 512.0f, &s, &c);
        stw[TWI(tid)] = make_float2(c, s);
    }
    for (int i = tid; i < MWIN; i += 256)        // periodic hann
        win[i] = 0.5f - 0.5f * cospif((float)i / 400.0f);
    __syncthreads();

    // windowed input, elements tid+256q held in registers (natural order)
    const float* yb = y + (size_t)b * TSAMP;
    float2 v[4];
    if (p >= 1 && p <= 132) {                    // interior: no reflect/bounds
        const float* pa = yb + fa * HOP - 512;
        const float* pb = yb + fb * HOP - 512;
        #pragma unroll
        for (int q = 0; q < 4; q++) {
            int j = tid + q * 256;
            float va = 0.0f, vb = 0.0f;
            if (j >= 112 && j < 912) {
                float w = win[j - 112];
                va = __ldg(pa + j) * w;
                vb = __ldg(pb + j) * w;
            }
            v[q] = make_float2(va, vb);
        }
    } else {                                     // edge frames: reflect pad
        #pragma unroll
        for (int q = 0; q < 4; q++) {
            int j = tid + q * 256;
            float va = 0.0f, vb = 0.0f;
            if (j >= 112 && j < 912) {
                float w = win[j - 112];
                int sa = fa * HOP + j - 512;
                if (sa < 0) sa = -sa;
                else if (sa >= TSAMP) sa = 2 * (TSAMP - 1) - sa;
                va = __ldg(yb + sa) * w;
                if (fb < NF) {
                    int sb = fb * HOP + j - 512;
                    if (sb < 0) sb = -sb;
                    else if (sb >= TSAMP) sb = 2 * (TSAMP - 1) - sb;
                    vb = __ldg(yb + sb) * w;
                }
            }
            v[q] = make_float2(va, vb);
        }
    }

    // stage 0 (Ns=1, twiddles = 1): registers -> B, contiguous STS.128 x2
    {
        float2 t0 = {v[0].x + v[2].x, v[0].y + v[2].y};
        float2 t1 = {v[0].x - v[2].x, v[0].y - v[2].y};
        float2 t2 = {v[1].x + v[3].x, v[1].y + v[3].y};
        float2 t3 = {v[1].x - v[3].x, v[1].y - v[3].y};
        ((float4*)B)[2 * tid]     = make_float4(t0.x + t2.x, t0.y + t2.y,
                                                t1.x + t3.y, t1.y - t3.x);
        ((float4*)B)[2 * tid + 1] = make_float4(t0.x - t2.x, t0.y - t2.y,
                                                t1.x - t3.y, t1.y + t3.x);
    }
    __syncthreads();

    #define BFLY(w1, v0, v1, v2, v3, o0, o1, o2, o3)                          \
        {                                                                     \
            float2 w2 = cmul(w1, w1), w3 = cmul(w1, w2);                      \
            float2 a1 = cmul(w1, v1), a2 = cmul(w2, v2), a3 = cmul(w3, v3);   \
            float2 t0 = {v0.x + a2.x, v0.y + a2.y};                           \
            float2 t1 = {v0.x - a2.x, v0.y - a2.y};                           \
            float2 t2 = {a1.x + a3.x, a1.y + a3.y};                           \
            float2 t3 = {a1.x - a3.x, a1.y - a3.y};                           \
            o0 = make_float2(t0.x + t2.x, t0.y + t2.y);                       \
            o1 = make_float2(t1.x + t3.y, t1.y - t3.x);                       \
            o2 = make_float2(t0.x - t2.x, t0.y - t2.y);                       \
            o3 = make_float2(t1.x - t3.y, t1.y + t3.x);                       \
        }

    // stage 1 (Ns=4): B -> A (PHI1 layout)
    {
        const int m = tid & 3;
        float2 v0 = B[tid], v1 = B[tid + 256], v2 = B[tid + 512], v3 = B[tid + 768];
        float2 w1 = stw[TWI(m * 64)];
        float2 o0, o1, o2, o3;
        BFLY(w1, v0, v1, v2, v3, o0, o1, o2, o3);
        const int base = ((tid >> 2) << 4) + m;
        A[PHI1(base)]      = o0; A[PHI1(base + 4)]  = o1;
        A[PHI1(base + 8)]  = o2; A[PHI1(base + 12)] = o3;
    }
    __syncthreads();

    // stage 2 (Ns=16): A (PHI1) -> B (identity)
    {
        const int m = tid & 15;
        float2 v0 = A[PHI1(tid)],       v1 = A[PHI1(tid + 256)];
        float2 v2 = A[PHI1(tid + 512)], v3 = A[PHI1(tid + 768)];
        float2 w1 = stw[TWI(m * 16)];
        float2 o0, o1, o2, o3;
        BFLY(w1, v0, v1, v2, v3, o0, o1, o2, o3);
        const int base = ((tid >> 4) << 6) + m;
        B[base]      = o0; B[base + 16] = o1;
        B[base + 32] = o2; B[base + 48] = o3;
    }
    __syncthreads();

    // stage 3 (Ns=64): B -> A (identity)
    {
        const int m = tid & 63;
        float2 v0 = B[tid], v1 = B[tid + 256], v2 = B[tid + 512], v3 = B[tid + 768];
        float2 w1 = stw[TWI(m * 4)];
        float2 o0, o1, o2, o3;
        BFLY(w1, v0, v1, v2, v3, o0, o1, o2, o3);
        const int base = ((tid >> 6) << 8) + m;
        A[base]       = o0; A[base + 64]  = o1;
        A[base + 128] = o2; A[base + 192] = o3;
    }
    __syncthreads();

    // stage 4 (Ns=256, trimmed): Z[tid] stays in regs; only Z[tid+768] -> smem
    float2 zk;
    {
        float2 v0 = A[tid], v1 = A[tid + 256], v2 = A[tid + 512], v3 = A[tid + 768];
        float2 w1 = stw[TWI(tid)];
        float2 w2 = cmul(w1, w1), w3 = cmul(w1, w2);
        float2 a1 = cmul(w1, v1), a2 = cmul(w2, v2), a3 = cmul(w3, v3);
        float2 t0 = {v0.x + a2.x, v0.y + a2.y};
        float2 t1 = {v0.x - a2.x, v0.y - a2.y};
        float2 t2 = {a1.x + a3.x, a1.y + a3.y};
        float2 t3 = {a1.x - a3.x, a1.y - a3.y};
        zk = make_float2(t0.x + t2.x, t0.y + t2.y);          // Z[tid]
        B[768 + tid] = make_float2(t1.x - t3.y, t1.y + t3.x); // Z[tid+768]
    }
    __syncthreads();

    // Hermitian unpack; power, layout [B, T, F] -> coalesced 256-bin stores
    float2 zc = (tid == 0) ? zk : B[1024 - tid];  // Z[K - tid]
    float xar = 0.5f * (zk.x + zc.x), xai = 0.5f * (zk.y - zc.y);
    float ddr = zk.x - zc.x,          ddi = zk.y + zc.y;
    float xbr = 0.5f * ddi,           xbi = -0.5f * ddr;
    g_Yt[((size_t)b * NF + fa) * NBINS + tid] = xar * xar + xai * xai;
    if (fb < NF)
        g_Yt[((size_t)b * NF + fb) * NBINS + tid] = xbr * xbr + xbi * xbi;
}

// ---------------- RT60 per (batch, subband): compact valid keys -------------
// Reads g_Yt strided (stride NBINS); sectors shared across 8 adjacent blocks
// via L2. Memory pipes here are nearly idle, so the sector cost hides.
__global__ __launch_bounds__(128) void rt60_kernel() {
    const int f = blockIdx.x % NBINS;
    const int b = blockIdx.x / NBINS;
    __shared__ float        sy[NF];
    __shared__ unsigned int W[12];               // decrease-flag bitmask (267 bits)
    __shared__ unsigned int skey[NF];
    __shared__ int          sbest;
    __shared__ int          scnt;
    __shared__ int          sbase;
    const int tid  = threadIdx.x;
    const int lane = tid & 31;
    if (tid < 12) W[tid] = 0u;
    if (tid == 0) { sbest = 0; scnt = 0; }

    const float* col = g_Yt + (size_t)b * NF * NBINS + f;
    for (int t = tid; t < NF; t += 128) sy[t] = __ldg(col + (size_t)t * NBINS);
    __syncthreads();

    // pack strict-decrease flags into bitmask words via ballot
    #pragma unroll
    for (int base = 0; base < 288; base += 128) {
        int t = base + tid;
        bool flag = (t + 1 < NF) && (sy[t + 1] < sy[t]);
        unsigned int m = __ballot_sync(0xFFFFFFFFu, flag);
        if (lane == 0 && (t >> 5) < 9) W[t >> 5] = m;
    }
    __syncthreads();

    // best window length: run length from t = ffs of first zero bit
    int localbest = 0;
    for (int t = tid; t < NF; t += 128) {
        int w = t >> 5, r = t & 31;
        unsigned int bits = (W[w] >> r) | (r ? (W[w + 1] << (32 - r)) : 0u);
        unsigned int nb = ~bits;
        int c = nb ? (__ffs(nb) - 1) : 32;
        if (c > LMAXW - 1) c = LMAXW - 1;
        int cand = c + 1;
        int rem  = NF - t;
        if (cand > rem) cand = rem;
        if (cand > localbest) localbest = cand;
    }
    atomicMax(&sbest, localbest);
    __syncthreads();

    const int lenL = sbest;
    if (lenL < LMINW) return;                    // no decreasing window at all

    const float xm  = 0.5f * (float)(lenL - 1);
    const float den = (float)lenL * (float)(lenL * lenL - 1) / 12.0f;

    for (int t = tid; t < NF; t += 128) {
        int w = t >> 5, r = t & 31;
        unsigned int bits = (W[w] >> r) | (r ? (W[w + 1] << (32 - r)) : 0u);
        unsigned int nb = ~bits;
        int c = nb ? (__ffs(nb) - 1) : 32;
        if (t + lenL <= NF && c >= lenL - 1) {
            // EDC: reverse cumsum in same order as reference, then dB
            float acc = 0.0f;
            float db[LMAXW];
            for (int j = lenL - 1; j >= 0; j--) {
                acc += sy[t + j];
                db[j] = 10.0f * log10f(fmaxf(acc, 1e-10f));
            }
            float d0 = db[0];
            if (db[lenL - 1] - d0 < -10.0f) {    // selected
                float num = 0.0f;
                for (int j = 1; j < lenL; j++)
                    num += ((float)j - xm) * (db[j] - d0);
                float slope = num / den;         // slope <= 0 here
                float rt60  = (-60.0f / slope) * 0.0375f;  // HOP/FS
                unsigned int u = __float_as_uint(rt60);
                unsigned int key = (u & 0x80000000u) ? ~u : (u | 0x80000000u);
                int pos = atomicAdd(&scnt, 1);   // smem atomic (cheap)
                skey[pos] = key;
            }
        }
    }
    __syncthreads();

    const int cnt = scnt;
    if (cnt == 0) return;
    if (tid == 0) sbase = atomicAdd(&g_nvalid[b], cnt);  // ONE global atomic
    __syncthreads();
    unsigned int* dst = g_keys + (size_t)b * FT + sbase;
    for (int i = tid; i < cnt; i += 128) dst[i] = skey[i];
}

// ---------------- median: one block per batch, 4-pass radix select ----------
__global__ __launch_bounds__(512) void median_kernel(const float* __restrict__ coeffs,
                                                     float* __restrict__ out) {
    const int b   = blockIdx.x;
    const int tid = threadIdx.x;
    __shared__ unsigned int skeys[SMEMK];
    __shared__ int          hist[256];
    __shared__ unsigned int s_pfx;
    __shared__ int          s_k;

    const int n = g_nvalid[b];
    if (n == 0) {
        if (tid == 0) out[b] = 0.5f;             // DEFAULT_RT60 (>= 0.01)
        return;
    }
    const unsigned int* gk = g_keys + (size_t)b * FT;
    const bool fits = (n <= SMEMK);
    if (fits)
        for (int i = tid; i < n; i += 512) skeys[i] = gk[i];
    if (tid == 0) { s_pfx = 0u; s_k = (n - 1) >> 1; }
    __syncthreads();

    #pragma unroll
    for (int pass = 0; pass < 4; pass++) {
        for (int i = tid; i < 256; i += 512) hist[i] = 0;
        __syncthreads();
        const int shift = 24 - 8 * pass;
        const unsigned int pfx   = s_pfx;
        const unsigned int hmask = (pass == 0) ? 0u : (0xFFFFFFFFu << (shift + 8));
        if (fits) {
            for (int i = tid; i < n; i += 512) {
                unsigned int key = skeys[i];
                if ((key & hmask) == pfx) atomicAdd(&hist[(key >> shift) & 255], 1);
            }
        } else {
            for (int i = tid; i < n; i += 512) {
                unsigned int key = gk[i];
                if ((key & hmask) == pfx) atomicAdd(&hist[(key >> shift) & 255], 1);
            }
        }
        __syncthreads();

        if (tid < 32) {                          // warp-scan bin select
            const int lane = tid;
            const int base = lane * 8;
            int c[8]; int s = 0;
            #pragma unroll
            for (int q = 0; q < 8; q++) { c[q] = hist[base + q]; s += c[q]; }
            int excl = s;
            #pragma unroll
            for (int off = 1; off < 32; off <<= 1) {
                int nn = __shfl_up_sync(0xFFFFFFFFu, excl, off);
                if (lane >= off) excl += nn;
            }
            excl -= s;                           // exclusive prefix across lanes
            const int k0 = s_k;
            int bin = 256, cumAt = 0, cum = excl;
            #pragma unroll
            for (int q = 0; q < 8; q++) {
                if (bin == 256 && cum + c[q] > k0) { bin = base + q; cumAt = cum; }
                cum += c[q];
            }
            unsigned int ball = __ballot_sync(0xFFFFFFFFu, bin < 256);
            int src = __ffs(ball) - 1;           // guaranteed: total >= k0+1
            if (lane == src) {
                s_k   = k0 - cumAt;
                s_pfx = pfx | ((unsigned int)bin << shift);
            }
        }
        __syncthreads();
    }

    if (tid == 0) {
        unsigned int key = s_pfx;
        unsigned int u = (key & 0x80000000u) ? (key ^ 0x80000000u) : ~key;
        float med = __uint_as_float(u);
        out[b] = fmaxf(coeffs[0] + coeffs[1] * med, 0.01f);
    }
}

// ---------------- launcher ---------------------------------------------------
extern "C" void kernel_launch(void* const* d_in, const int* in_sizes, int n_in,
                              void* d_out, int out_size) {
    const float* y      = (const float*)d_in[0];
    const float* coeffs = (const float*)d_in[1];
    float*       out    = (float*)d_out;

    stft_kernel<<<NB * NFP, 256>>>(y);
    rt60_kernel<<<NB * NBINS, 128>>>();
    median_kernel<<<NB, 512>>>(coeffs, out);
}

// round 16
// speedup vs baseline: 1.1333x; 1.1112x over previous
#include <cuda_runtime.h>
#include <math.h>

// ---------------- problem constants (fixed shapes from setup_inputs) -------
#define NB      32          // batch
#define TSAMP   160000      // samples per batch
#define KFFT    1024        // n_fft
#define MWIN    800         // win_length
#define HOP     600
#define NBINS   256
#define NF      267         // 1 + (160000+1024-1024)/600
#define NFP     134         // frame pairs (two real frames per complex FFT)
#define NFQ2    67          // two FFTs (4 frames) per block
#define LMAXW   13
#define LMINW   3
#define FT      (NBINS*NF)  // 68352 (worst-case valid keys per batch)
#define SMEMK   8192        // median smem key cache capacity

#define PHIc(a) ((a) + ((a) >> 4))   // skewed FFT exchange buffer layout
#define TWI(i)  ((i) + ((i) >> 4))   // skewed twiddle index (CF strided reads)

__device__ __forceinline__ float2 cmul(float2 a, float2 b) {
    return make_float2(a.x * b.x - a.y * b.y, a.x * b.y + a.y * b.x);
}

// ---------------- scratch (__device__ globals, no allocation) --------------
__device__ float        g_Yt[NB*NF*NBINS];      // [B, T, F]: stft-coalesced
__device__ unsigned int g_keys[NB*FT];          // compacted valid keys
__device__ int          g_nvalid[NB];

// ---------------- STFT power: fused-stage-pair radix-4 FFT ------------------
// 64 threads per 1024-pt complex FFT (2 real frames packed), 16 elements per
// thread. Stages 0+1 fused in registers, one skewed smem exchange, stages
// 2+3 fused, one exchange, trimmed stage 4 + Hermitian unpack. Arithmetic is
// bit-identical to the 5-stage Stockham version (same twiddles, same order).
__global__ __launch_bounds__(128) void stft_kernel(const float* __restrict__ y) {
    const int bq  = blockIdx.x % NFQ2;
    const int b   = blockIdx.x / NFQ2;
    const int tid = threadIdx.x;
    const int e   = tid >> 6;                    // FFT slot within block (0/1)
    const int u   = tid & 63;                    // lane within FFT
    const int p   = bq * 2 + e;
    const int fa  = 2 * p;
    const int fb  = 2 * p + 1;                   // may be NF (dropped)

    __shared__ float2 buf1[2][1088];             // PHIc(1023)=1086 < 1088
    __shared__ float2 buf2[2][1088];
    __shared__ float2 Wt[272];                   // w^j, j<256, TWI-skewed
    __shared__ float  win[MWIN];

    if (bq == 0 && tid == 0) g_nvalid[b] = 0;    // replay-state reset

    {   // twiddle table: exp(-2*pi*i*j/1024), j<256
        float s, c;
        sincospif(-(float)tid / 512.0f, &s, &c);
        Wt[TWI(tid)] = make_float2(c, s);
        sincospif(-(float)(tid + 128) / 512.0f, &s, &c);
        Wt[TWI(tid + 128)] = make_float2(c, s);
    }
    for (int i = tid; i < MWIN; i += 128)        // periodic hann
        win[i] = 0.5f - 0.5f * cospif((float)i / 400.0f);
    __syncthreads();

    float2* B1 = buf1[e];
    float2* B2 = buf2[e];

    // ---- load 16 windowed elements: X[a][c] = x[u + 64a + 256c] -----------
    const float* yb = y + (size_t)b * TSAMP;
    float2 X[4][4];
    if (p >= 1 && p <= 132) {                    // interior: no reflect/bounds
        const float* pa = yb + fa * HOP - 512;
        const float* pb = yb + fb * HOP - 512;
        #pragma unroll
        for (int a = 0; a < 4; a++)
        #pragma unroll
        for (int c = 0; c < 4; c++) {
            int j = u + 64 * a + 256 * c;
            float va = 0.0f, vb = 0.0f;
            if (j >= 112 && j < 912) {           // zero-padded centered window
                float w = win[j - 112];
                va = __ldg(pa + j) * w;
                vb = __ldg(pb + j) * w;
            }
            X[a][c] = make_float2(va, vb);
        }
    } else {                                     // edge frames: reflect pad
        #pragma unroll
        for (int a = 0; a < 4; a++)
        #pragma unroll
        for (int c = 0; c < 4; c++) {
            int j = u + 64 * a + 256 * c;
            float va = 0.0f, vb = 0.0f;
            if (j >= 112 && j < 912) {
                float w = win[j - 112];
                int sa = fa * HOP + j - 512;     // center=True: pad K/2 = 512
                if (sa < 0) sa = -sa;
                else if (sa >= TSAMP) sa = 2 * (TSAMP - 1) - sa;
                va = __ldg(yb + sa) * w;
                if (fb < NF) {
                    int sb = fb * HOP + j - 512;
                    if (sb < 0) sb = -sb;
                    else if (sb >= TSAMP) sb = 2 * (TSAMP - 1) - sb;
                    vb = __ldg(yb + sb) * w;
                }
            }
            X[a][c] = make_float2(va, vb);
        }
    }

    // ---- fused stages 0+1 (registers) -> B1 --------------------------------
    // stage 0 (Ns=1, w=1): butterfly g=u+64a on inputs X[a][c]
    float2 s0[4][4];
    #pragma unroll
    for (int a = 0; a < 4; a++) {
        float2 v0 = X[a][0], v1 = X[a][1], v2 = X[a][2], v3 = X[a][3];
        float2 t0 = {v0.x+v2.x, v0.y+v2.y}, t1 = {v0.x-v2.x, v0.y-v2.y};
        float2 t2 = {v1.x+v3.x, v1.y+v3.y}, t3 = {v1.x-v3.x, v1.y-v3.y};
        s0[a][0] = make_float2(t0.x+t2.x, t0.y+t2.y);
        s0[a][1] = make_float2(t1.x+t3.y, t1.y-t3.x);
        s0[a][2] = make_float2(t0.x-t2.x, t0.y-t2.y);
        s0[a][3] = make_float2(t1.x-t3.y, t1.y+t3.x);
    }
    // stage 1 (Ns=4): butterfly k1=4u+r consumes s0[c][r]; writes [16u,16u+16)
    #pragma unroll
    for (int r = 0; r < 4; r++) {
        float2 v0 = s0[0][r], a1 = s0[1][r], a2 = s0[2][r], a3 = s0[3][r];
        if (r > 0) {
            float2 w1 = Wt[TWI(64 * r)];
            float2 w2 = cmul(w1, w1), w3 = cmul(w1, w2);
            a1 = cmul(w1, a1); a2 = cmul(w2, a2); a3 = cmul(w3, a3);
        }
        float2 t0 = {v0.x+a2.x, v0.y+a2.y}, t1 = {v0.x-a2.x, v0.y-a2.y};
        float2 t2 = {a1.x+a3.x, a1.y+a3.y}, t3 = {a1.x-a3.x, a1.y-a3.y};
        const int base = 16 * u + r;
        B1[PHIc(base)]      = make_float2(t0.x+t2.x, t0.y+t2.y);
        B1[PHIc(base + 4)]  = make_float2(t1.x+t3.y, t1.y-t3.x);
        B1[PHIc(base + 8)]  = make_float2(t0.x-t2.x, t0.y-t2.y);
        B1[PHIc(base + 12)] = make_float2(t1.x-t3.y, t1.y+t3.x);
    }
    __syncthreads();

    // ---- fused stages 2+3 (registers) -> B2 --------------------------------
    const int m2 = u & 15, q2 = u >> 4;
    float2 V[4][4];
    #pragma unroll
    for (int c1 = 0; c1 < 4; c1++)
    #pragma unroll
    for (int d = 0; d < 4; d++)
        V[c1][d] = B1[PHIc(u + 64 * c1 + 256 * d)];

    // stage 2 (Ns=16): butterflies u+64c1, m=(u&15), outputs s2[c1][c]
    float2 s2[4][4];
    {
        float2 w1 = Wt[TWI(16 * m2)];
        float2 w2 = cmul(w1, w1), w3 = cmul(w1, w2);
        #pragma unroll
        for (int c1 = 0; c1 < 4; c1++) {
            float2 v0 = V[c1][0];
            float2 a1 = cmul(w1, V[c1][1]);
            float2 a2 = cmul(w2, V[c1][2]);
            float2 a3 = cmul(w3, V[c1][3]);
            float2 t0 = {v0.x+a2.x, v0.y+a2.y}, t1 = {v0.x-a2.x, v0.y-a2.y};
            float2 t2 = {a1.x+a3.x, a1.y+a3.y}, t3 = {a1.x-a3.x, a1.y-a3.y};
            s2[c1][0] = make_float2(t0.x+t2.x, t0.y+t2.y);
            s2[c1][1] = make_float2(t1.x+t3.y, t1.y-t3.x);
            s2[c1][2] = make_float2(t0.x-t2.x, t0.y-t2.y);
            s2[c1][3] = make_float2(t1.x-t3.y, t1.y+t3.x);
        }
    }
    // stage 3 (Ns=64): butterflies k3 = 64*q2 + m2 + 16c, m3 = m2+16c
    #pragma unroll
    for (int c = 0; c < 4; c++) {
        float2 w1 = Wt[TWI(4 * m2 + 64 * c)];
        float2 w2 = cmul(w1, w1), w3 = cmul(w1, w2);
        float2 v0 = s2[0][c];
        float2 a1 = cmul(w1, s2[1][c]);
        float2 a2 = cmul(w2, s2[2][c]);
        float2 a3 = cmul(w3, s2[3][c]);
        float2 t0 = {v0.x+a2.x, v0.y+a2.y}, t1 = {v0.x-a2.x, v0.y-a2.y};
        float2 t2 = {a1.x+a3.x, a1.y+a3.y}, t3 = {a1.x-a3.x, a1.y-a3.y};
        const int base = 256 * q2 + m2 + 16 * c;
        B2[PHIc(base)]       = make_float2(t0.x+t2.x, t0.y+t2.y);
        B2[PHIc(base + 64)]  = make_float2(t1.x+t3.y, t1.y-t3.x);
        B2[PHIc(base + 128)] = make_float2(t0.x-t2.x, t0.y-t2.y);
        B2[PHIc(base + 192)] = make_float2(t1.x-t3.y, t1.y+t3.x);
    }
    __syncthreads();

    // ---- stage 4 (Ns=256, trimmed): Z[k4] and Z[k4+768] only ---------------
    float2 Vz[4][4];
    #pragma unroll
    for (int d = 0; d < 4; d++)
    #pragma unroll
    for (int c = 0; c < 4; c++)
        Vz[d][c] = B2[PHIc(u + 64 * d + 256 * c)];
    #pragma unroll
    for (int d = 0; d < 4; d++) {
        const int k4 = u + 64 * d;
        float2 w1 = Wt[TWI(k4)];
        float2 w2 = cmul(w1, w1), w3 = cmul(w1, w2);
        float2 v0 = Vz[d][0];
        float2 a1 = cmul(w1, Vz[d][1]);
        float2 a2 = cmul(w2, Vz[d][2]);
        float2 a3 = cmul(w3, Vz[d][3]);
        float2 t0 = {v0.x+a2.x, v0.y+a2.y}, t1 = {v0.x-a2.x, v0.y-a2.y};
        float2 t2 = {a1.x+a3.x, a1.y+a3.y}, t3 = {a1.x-a3.x, a1.y-a3.y};
        B1[k4]       = make_float2(t0.x+t2.x, t0.y+t2.y);   // Z[k4]
        B1[256 + k4] = make_float2(t1.x-t3.y, t1.y+t3.x);   // Z[k4+768]
    }
    __syncthreads();

    // ---- Hermitian unpack; power, layout [B, T, F] -------------------------
    float* Ya = g_Yt + ((size_t)b * NF + fa) * NBINS;
    float* Yb = g_Yt + ((size_t)b * NF + fb) * NBINS;
    #pragma unroll
    for (int i = 0; i < 4; i++) {
        const int k = u + 64 * i;
        float2 zk = B1[k];
        float2 zc = (k == 0) ? zk : B1[512 - k];  // Z[1024-k] = Zhi[256-k]
        float xar = 0.5f * (zk.x + zc.x), xai = 0.5f * (zk.y - zc.y);
        float ddr = zk.x - zc.x,          ddi = zk.y + zc.y;
        float xbr = 0.5f * ddi,           xbi = -0.5f * ddr;
        Ya[k] = xar * xar + xai * xai;
        if (fb < NF) Yb[k] = xbr * xbr + xbi * xbi;
    }
}

// ---------------- RT60 per (batch, subband): compact valid keys -------------
__global__ __launch_bounds__(128) void rt60_kernel() {
    const int f = blockIdx.x % NBINS;
    const int b = blockIdx.x / NBINS;
    __shared__ float        sy[NF];
    __shared__ unsigned int W[12];               // decrease-flag bitmask (267 bits)
    __shared__ unsigned int skey[NF];
    __shared__ int          sbest;
    __shared__ int          scnt;
    __shared__ int          sbase;
    const int tid  = threadIdx.x;
    const int lane = tid & 31;
    if (tid < 12) W[tid] = 0u;
    if (tid == 0) { sbest = 0; scnt = 0; }

    const float* col = g_Yt + (size_t)b * NF * NBINS + f;
    for (int t = tid; t < NF; t += 128) sy[t] = __ldg(col + (size_t)t * NBINS);
    __syncthreads();

    // pack strict-decrease flags into bitmask words via ballot
    #pragma unroll
    for (int base = 0; base < 288; base += 128) {
        int t = base + tid;
        bool flag = (t + 1 < NF) && (sy[t + 1] < sy[t]);
        unsigned int m = __ballot_sync(0xFFFFFFFFu, flag);
        if (lane == 0 && (t >> 5) < 9) W[t >> 5] = m;
    }
    __syncthreads();

    // best window length: run length from t = ffs of first zero bit
    int localbest = 0;
    for (int t = tid; t < NF; t += 128) {
        int w = t >> 5, r = t & 31;
        unsigned int bits = (W[w] >> r) | (r ? (W[w + 1] << (32 - r)) : 0u);
        unsigned int nb = ~bits;
        int c = nb ? (__ffs(nb) - 1) : 32;
        if (c > LMAXW - 1) c = LMAXW - 1;
        int cand = c + 1;
        int rem  = NF - t;
        if (cand > rem) cand = rem;
        if (cand > localbest) localbest = cand;
    }
    atomicMax(&sbest, localbest);
    __syncthreads();

    const int lenL = sbest;
    if (lenL < LMINW) return;                    // no decreasing window at all

    const float xm  = 0.5f * (float)(lenL - 1);
    const float den = (float)lenL * (float)(lenL * lenL - 1) / 12.0f;

    for (int t = tid; t < NF; t += 128) {
        int w = t >> 5, r = t & 31;
        unsigned int bits = (W[w] >> r) | (r ? (W[w + 1] << (32 - r)) : 0u);
        unsigned int nb = ~bits;
        int c = nb ? (__ffs(nb) - 1) : 32;
        if (t + lenL <= NF && c >= lenL - 1) {
            // EDC: reverse cumsum in same order as reference, then dB
            float acc = 0.0f;
            float db[LMAXW];
            for (int j = lenL - 1; j >= 0; j--) {
                acc += sy[t + j];
                db[j] = 10.0f * log10f(fmaxf(acc, 1e-10f));
            }
            float d0 = db[0];
            if (db[lenL - 1] - d0 < -10.0f) {    // selected
                float num = 0.0f;
                for (int j = 1; j < lenL; j++)
                    num += ((float)j - xm) * (db[j] - d0);
                float slope = num / den;         // slope <= 0 here
                float rt60  = (-60.0f / slope) * 0.0375f;  // HOP/FS
                unsigned int uu = __float_as_uint(rt60);
                unsigned int key = (uu & 0x80000000u) ? ~uu : (uu | 0x80000000u);
                int pos = atomicAdd(&scnt, 1);   // smem atomic (cheap)
                skey[pos] = key;
            }
        }
    }
    __syncthreads();

    const int cnt = scnt;
    if (cnt == 0) return;
    if (tid == 0) sbase = atomicAdd(&g_nvalid[b], cnt);  // ONE global atomic
    __syncthreads();
    unsigned int* dst = g_keys + (size_t)b * FT + sbase;
    for (int i = tid; i < cnt; i += 128) dst[i] = skey[i];
}

// ---------------- median: one block per batch, 4-pass radix select ----------
__global__ __launch_bounds__(512) void median_kernel(const float* __restrict__ coeffs,
                                                     float* __restrict__ out) {
    const int b   = blockIdx.x;
    const int tid = threadIdx.x;
    __shared__ unsigned int skeys[SMEMK];
    __shared__ int          hist[256];
    __shared__ unsigned int s_pfx;
    __shared__ int          s_k;

    const int n = g_nvalid[b];
    if (n == 0) {
        if (tid == 0) out[b] = 0.5f;             // DEFAULT_RT60 (>= 0.01)
        return;
    }
    const unsigned int* gk = g_keys + (size_t)b * FT;
    const bool fits = (n <= SMEMK);
    if (fits)
        for (int i = tid; i < n; i += 512) skeys[i] = gk[i];
    if (tid == 0) { s_pfx = 0u; s_k = (n - 1) >> 1; }
    __syncthreads();

    #pragma unroll
    for (int pass = 0; pass < 4; pass++) {
        for (int i = tid; i < 256; i += 512) hist[i] = 0;
        __syncthreads();
        const int shift = 24 - 8 * pass;
        const unsigned int pfx   = s_pfx;
        const unsigned int hmask = (pass == 0) ? 0u : (0xFFFFFFFFu << (shift + 8));
        if (fits) {
            for (int i = tid; i < n; i += 512) {
                unsigned int key = skeys[i];
                if ((key & hmask) == pfx) atomicAdd(&hist[(key >> shift) & 255], 1);
            }
        } else {
            for (int i = tid; i < n; i += 512) {
                unsigned int key = gk[i];
                if ((key & hmask) == pfx) atomicAdd(&hist[(key >> shift) & 255], 1);
            }
        }
        __syncthreads();

        if (tid < 32) {                          // warp-scan bin select
            const int lane = tid;
            const int base = lane * 8;
            int c[8]; int s = 0;
            #pragma unroll
            for (int q = 0; q < 8; q++) { c[q] = hist[base + q]; s += c[q]; }
            int excl = s;
            #pragma unroll
            for (int off = 1; off < 32; off <<= 1) {
                int nn = __shfl_up_sync(0xFFFFFFFFu, excl, off);
                if (lane >= off) excl += nn;
            }
            excl -= s;                           // exclusive prefix across lanes
            const int k0 = s_k;
            int bin = 256, cumAt = 0, cum = excl;
            #pragma unroll
            for (int q = 0; q < 8; q++) {
                if (bin == 256 && cum + c[q] > k0) { bin = base + q; cumAt = cum; }
                cum += c[q];
            }
            unsigned int ball = __ballot_sync(0xFFFFFFFFu, bin < 256);
            int src = __ffs(ball) - 1;           // guaranteed: total >= k0+1
            if (lane == src) {
                s_k   = k0 - cumAt;
                s_pfx = pfx | ((unsigned int)bin << shift);
            }
        }
        __syncthreads();
    }

    if (tid == 0) {
        unsigned int key = s_pfx;
        unsigned int u = (key & 0x80000000u) ? (key ^ 0x80000000u) : ~key;
        float med = __uint_as_float(u);
        out[b] = fmaxf(coeffs[0] + coeffs[1] * med, 0.01f);
    }
}

// ---------------- launcher ---------------------------------------------------
extern "C" void kernel_launch(void* const* d_in, const int* in_sizes, int n_in,
                              void* d_out, int out_size) {
    const float* y      = (const float*)d_in[0];
    const float* coeffs = (const float*)d_in[1];
    float*       out    = (float*)d_out;

    stft_kernel<<<NB * NFQ2, 128>>>(y);
    rt60_kernel<<<NB * NBINS, 128>>>();
    median_kernel<<<NB, 512>>>(coeffs, out);
}